// round 1
// baseline (speedup 1.0000x reference)
#include <cuda_runtime.h>
#include <math.h>

// Problem constants (shapes fixed by the dataset)
#define NN 50000
#define EE 800000
#define DD 128
#define NH 8
#define NG 64
#define NC 10
#define NEG_SLOPE 0.2f

// ---------------- scratch (device globals: allocation-free) ----------------
__device__ __align__(16) float g_bufA[NN * DD];
__device__ __align__(16) float g_bufB[NN * DD];
__device__ __align__(16) float g_xl[NN * DD];
__device__ __align__(16) float g_xr[NN * DD];
__device__ int   g_deg[NN];
__device__ int   g_rowptr[NN + 1];
__device__ int   g_cursor[NN];
__device__ int   g_csr[EE];
__device__ __align__(16) float g_pooled[NG * DD];
__device__ int   g_cnt[NG];

// ---------------- CSR build ----------------
__global__ void zero_kernel() {
    int stride = gridDim.x * blockDim.x;
    int t0 = blockIdx.x * blockDim.x + threadIdx.x;
    for (int i = t0; i < NN; i += stride) g_deg[i] = 0;
    for (int i = t0; i < NG * DD; i += stride) g_pooled[i] = 0.f;
    for (int i = t0; i < NG; i += stride) g_cnt[i] = 0;
}

__global__ void hist_kernel(const int* __restrict__ dst, int E) {
    int i = blockIdx.x * blockDim.x + threadIdx.x;
    if (i < E) atomicAdd(&g_deg[dst[i]], 1);
}

// single-block exclusive scan over g_deg[0..n) -> g_rowptr / g_cursor
__global__ void scan_kernel(int n) {
    __shared__ int s[1024];
    int t = threadIdx.x;
    int CH = (n + 1023) >> 10;
    int lo = t * CH;
    int hi = min(lo + CH, n);
    int sum = 0;
    for (int i = lo; i < hi; i++) sum += g_deg[i];
    s[t] = sum;
    __syncthreads();
    for (int off = 1; off < 1024; off <<= 1) {
        int v = s[t];
        if (t >= off) v += s[t - off];
        __syncthreads();
        s[t] = v;
        __syncthreads();
    }
    int run = s[t] - sum;   // exclusive prefix for this chunk
    for (int i = lo; i < hi; i++) {
        g_rowptr[i] = run;
        g_cursor[i] = run;
        run += g_deg[i];
    }
    if (t == 1023) g_rowptr[n] = s[1023];
}

__global__ void scatter_kernel(const int* __restrict__ src,
                               const int* __restrict__ dst, int E) {
    int i = blockIdx.x * blockDim.x + threadIdx.x;
    if (i < E) {
        int d = dst[i];
        int pos = atomicAdd(&g_cursor[d], 1);
        g_csr[pos] = src[i];
    }
}

// ---------------- GEMM: C = A[ n x 128 ] @ W[128 x 128] + b ----------------
// blockIdx.y == 0 -> (Wl, bl) -> g_xl ; blockIdx.y == 1 -> (Wr, br) -> g_xr
// 64x128 output tile per block, 128 threads, 8x8 register tile per thread.
__global__ void __launch_bounds__(128) gemm_kernel(
    const float* __restrict__ xext, int src_sel,
    const float* __restrict__ Wl, const float* __restrict__ bl,
    const float* __restrict__ Wr, const float* __restrict__ br, int n)
{
    const float* A = (src_sel == 0) ? xext : (src_sel == 1 ? g_bufA : g_bufB);
    const float* W = blockIdx.y ? Wr : Wl;
    const float* b = blockIdx.y ? br : bl;
    float* C       = blockIdx.y ? g_xr : g_xl;

    __shared__ __align__(16) float Ast[16][64];   // A tile, transposed [k][row]
    __shared__ __align__(16) float Ws[16][128];   // W tile [k][col]

    int row0 = blockIdx.x * 64;
    int tid = threadIdx.x;
    int tx = tid & 15;        // col group: cols tx*8 .. tx*8+7
    int ty = tid >> 4;        // row group: rows ty*8 .. ty*8+7

    float acc[8][8];
#pragma unroll
    for (int i = 0; i < 8; i++)
#pragma unroll
        for (int j = 0; j < 8; j++) acc[i][j] = 0.f;

    for (int kk = 0; kk < DD; kk += 16) {
        // load A tile (64 rows x 16 k), store transposed
#pragma unroll
        for (int i = 0; i < 2; i++) {
            int f = tid * 2 + i;          // 0..255 float4 slots
            int r = f >> 2;               // row within tile
            int k4 = (f & 3) << 2;        // k offset
            float4 v = make_float4(0.f, 0.f, 0.f, 0.f);
            int grow = row0 + r;
            if (grow < n)
                v = *(const float4*)(A + (size_t)grow * DD + kk + k4);
            Ast[k4 + 0][r] = v.x;
            Ast[k4 + 1][r] = v.y;
            Ast[k4 + 2][r] = v.z;
            Ast[k4 + 3][r] = v.w;
        }
        // load W tile (16 k x 128 cols)
#pragma unroll
        for (int i = 0; i < 4; i++) {
            int f = tid + i * 128;        // 0..511 float4 slots
            int kr = f >> 5;
            int c4 = (f & 31) << 2;
            *(float4*)&Ws[kr][c4] =
                *(const float4*)(W + (size_t)(kk + kr) * DD + c4);
        }
        __syncthreads();

#pragma unroll
        for (int k = 0; k < 16; k++) {
            float rm[8], rn[8];
            *(float4*)&rm[0] = *(const float4*)&Ast[k][ty * 8];
            *(float4*)&rm[4] = *(const float4*)&Ast[k][ty * 8 + 4];
            *(float4*)&rn[0] = *(const float4*)&Ws[k][tx * 8];
            *(float4*)&rn[4] = *(const float4*)&Ws[k][tx * 8 + 4];
#pragma unroll
            for (int i2 = 0; i2 < 8; i2++)
#pragma unroll
                for (int j = 0; j < 8; j++)
                    acc[i2][j] = fmaf(rm[i2], rn[j], acc[i2][j]);
        }
        __syncthreads();
    }

    float bj[8];
#pragma unroll
    for (int j = 0; j < 8; j++) bj[j] = b[tx * 8 + j];
#pragma unroll
    for (int i = 0; i < 8; i++) {
        int grow = row0 + ty * 8 + i;
        if (grow < n) {
            float4 o0, o1;
            o0.x = acc[i][0] + bj[0];
            o0.y = acc[i][1] + bj[1];
            o0.z = acc[i][2] + bj[2];
            o0.w = acc[i][3] + bj[3];
            o1.x = acc[i][4] + bj[4];
            o1.y = acc[i][5] + bj[5];
            o1.z = acc[i][6] + bj[6];
            o1.w = acc[i][7] + bj[7];
            *(float4*)(C + (size_t)grow * DD + tx * 8)     = o0;
            *(float4*)(C + (size_t)grow * DD + tx * 8 + 4) = o1;
        }
    }
}

// ---------------- fused GATv2 edge phase: warp per dst node ----------------
// Streaming (flash-style) softmax over incoming edges + implicit self loop.
// lane l covers cols 4l..4l+3 ; head = l>>2 ; att flat index == column index.
__global__ void __launch_bounds__(256) attn_kernel(
    const float* __restrict__ att, const float* __restrict__ bias,
    int dst_sel, int n)
{
    int gw = (blockIdx.x * blockDim.x + threadIdx.x) >> 5;
    if (gw >= n) return;
    int lane = threadIdx.x & 31;
    float* out = (dst_sel == 1) ? g_bufA : g_bufB;
    int v = gw;

    float4 xrv = *(const float4*)(g_xr + (size_t)v * DD + lane * 4);
    float4 a4  = *(const float4*)(att + lane * 4);
    float4 b4  = *(const float4*)(bias + lane * 4);

    float m = -3.402823466e38f;   // -FLT_MAX
    float den = 0.f;
    float4 acc = make_float4(0.f, 0.f, 0.f, 0.f);

    int e0 = g_rowptr[v], e1 = g_rowptr[v + 1];
    for (int e = e0; e <= e1; e++) {           // e == e1 -> self loop
        int u = (e < e1) ? g_csr[e] : v;
        float4 xu = *(const float4*)(g_xl + (size_t)u * DD + lane * 4);
        float t0 = xu.x + xrv.x; t0 = (t0 > 0.f) ? t0 : NEG_SLOPE * t0;
        float t1 = xu.y + xrv.y; t1 = (t1 > 0.f) ? t1 : NEG_SLOPE * t1;
        float t2 = xu.z + xrv.z; t2 = (t2 > 0.f) ? t2 : NEG_SLOPE * t2;
        float t3 = xu.w + xrv.w; t3 = (t3 > 0.f) ? t3 : NEG_SLOPE * t3;
        float s = a4.x * t0 + a4.y * t1 + a4.z * t2 + a4.w * t3;
        // reduce within the 4-lane head group (lanes 4h..4h+3)
        s += __shfl_xor_sync(0xffffffffu, s, 1);
        s += __shfl_xor_sync(0xffffffffu, s, 2);
        float nm = fmaxf(m, s);
        float c = __expf(m - nm);      // 0 on first edge (m = -FLT_MAX)
        float p = __expf(s - nm);
        den = den * c + p;
        acc.x = acc.x * c + p * xu.x;
        acc.y = acc.y * c + p * xu.y;
        acc.z = acc.z * c + p * xu.z;
        acc.w = acc.w * c + p * xu.w;
        m = nm;
    }
    float inv = 1.f / den;
    float4 o;
    o.x = acc.x * inv + b4.x;
    o.y = acc.y * inv + b4.y;
    o.z = acc.z * inv + b4.z;
    o.w = acc.w * inv + b4.w;
    // elu
    o.x = (o.x > 0.f) ? o.x : expm1f(o.x);
    o.y = (o.y > 0.f) ? o.y : expm1f(o.y);
    o.z = (o.z > 0.f) ? o.z : expm1f(o.z);
    o.w = (o.w > 0.f) ? o.w : expm1f(o.w);
    *(float4*)(out + (size_t)v * DD + lane * 4) = o;
}

// ---------------- global mean pool (accumulate) ----------------
__global__ void pool_kernel(const int* __restrict__ batch, int n) {
    int i = blockIdx.x * blockDim.x + threadIdx.x;
    int node = i >> 5;
    if (node >= n) return;
    int lane = i & 31;
    int g = batch[node];
    float4 v = *(const float4*)(g_bufA + (size_t)node * DD + lane * 4);
    atomicAdd(&g_pooled[g * DD + lane * 4 + 0], v.x);
    atomicAdd(&g_pooled[g * DD + lane * 4 + 1], v.y);
    atomicAdd(&g_pooled[g * DD + lane * 4 + 2], v.z);
    atomicAdd(&g_pooled[g * DD + lane * 4 + 3], v.w);
    if (lane == 0) atomicAdd(&g_cnt[g], 1);
}

// ---------------- output head: mean, logits, log_softmax ----------------
__global__ void head_kernel(const float* __restrict__ Wout,
                            const float* __restrict__ bout,
                            float* __restrict__ out) {
    int g = blockIdx.x;
    int lane = threadIdx.x;   // 32 threads
    float invc = 1.f / fmaxf((float)g_cnt[g], 1.f);
    float part[NC];
#pragma unroll
    for (int c = 0; c < NC; c++) part[c] = 0.f;
    for (int col = lane; col < DD; col += 32) {
        float v = g_pooled[g * DD + col] * invc;
#pragma unroll
        for (int c = 0; c < NC; c++) part[c] += v * Wout[col * NC + c];
    }
#pragma unroll
    for (int c = 0; c < NC; c++) {
#pragma unroll
        for (int off = 16; off; off >>= 1)
            part[c] += __shfl_xor_sync(0xffffffffu, part[c], off);
    }
    if (lane == 0) {
        float lg[NC];
        float mx = -3.402823466e38f;
#pragma unroll
        for (int c = 0; c < NC; c++) {
            lg[c] = part[c] + bout[c];
            mx = fmaxf(mx, lg[c]);
        }
        float se = 0.f;
#pragma unroll
        for (int c = 0; c < NC; c++) se += expf(lg[c] - mx);
        float lse = logf(se) + mx;
#pragma unroll
        for (int c = 0; c < NC; c++) out[g * NC + c] = lg[c] - lse;
    }
}

// ---------------- launch ----------------
extern "C" void kernel_launch(void* const* d_in, const int* in_sizes, int n_in,
                              void* d_out, int out_size) {
    const float* x     = (const float*)d_in[0];
    const int*   ei    = (const int*)d_in[1];
    const int*   batch = (const int*)d_in[2];
    const float* Wl    = (const float*)d_in[3];
    const float* bl    = (const float*)d_in[4];
    const float* Wr    = (const float*)d_in[5];
    const float* br    = (const float*)d_in[6];
    const float* att   = (const float*)d_in[7];
    const float* bias  = (const float*)d_in[8];
    const float* Wout  = (const float*)d_in[9];
    const float* bout  = (const float*)d_in[10];
    float* out = (float*)d_out;

    int N = in_sizes[0] / DD;
    int E = in_sizes[1] / 2;
    const int* srcp = ei;
    const int* dstp = ei + E;

    zero_kernel<<<256, 256>>>();
    hist_kernel<<<(E + 255) / 256, 256>>>(dstp, E);
    scan_kernel<<<1, 1024>>>(N);
    scatter_kernel<<<(E + 255) / 256, 256>>>(srcp, dstp, E);

    for (int l = 0; l < 5; l++) {
        int src_sel = (l == 0) ? 0 : ((l & 1) ? 1 : 2);
        int dst_sel = (l & 1) ? 2 : 1;
        dim3 gg((N + 63) / 64, 2);
        gemm_kernel<<<gg, 128>>>(x, src_sel,
                                 Wl + (size_t)l * DD * DD, bl + (size_t)l * DD,
                                 Wr + (size_t)l * DD * DD, br + (size_t)l * DD, N);
        int blocks = (N * 32 + 255) / 256;
        attn_kernel<<<blocks, 256>>>(att + (size_t)l * DD,
                                     bias + (size_t)l * DD, dst_sel, N);
    }
    pool_kernel<<<(N * 32 + 255) / 256, 256>>>(batch, N);
    head_kernel<<<NG, 32>>>(Wout, bout, out);
}

// round 3
// speedup vs baseline: 1.2190x; 1.2190x over previous
#include <cuda_runtime.h>
#include <cuda_bf16.h>
#include <math.h>
#include <stdint.h>

// Problem constants
#define NN 50000
#define EE 800000
#define DD 128
#define NG 64
#define NC 10
#define NEG_SLOPE 0.2f
#define NLAY 5

// ================= scratch =================
__device__ __align__(16) float g_bufA[NN * DD];
__device__ __align__(16) float g_bufB[NN * DD];
__device__ __align__(16) float g_xl[NN * DD];
__device__ __align__(16) float g_xr[NN * DD];
__device__ int   g_deg[NN];
__device__ int   g_rowptr[NN + 1];
__device__ int   g_cursor[NN];
__device__ int   g_csr[EE];
__device__ __align__(16) float g_pooled[NG * DD];
__device__ int   g_cnt[NG];
// Pre-split, pre-swizzled weight images: [layer][l/r][128 n-rows x 128 k] bf16
__device__ __align__(16) unsigned short g_Whi[NLAY][2][16384];
__device__ __align__(16) unsigned short g_Wlo[NLAY][2][16384];

__device__ __forceinline__ uint32_t smem_to_u32(const void* p) {
    uint32_t a;
    asm("{ .reg .u64 t; cvta.to.shared.u64 t, %1; cvt.u32.u64 %0, t; }" : "=r"(a) : "l"(p));
    return a;
}
__device__ __forceinline__ void ldsm_x4(uint32_t* r, uint32_t addr) {
    asm volatile("ldmatrix.sync.aligned.m8n8.x4.shared.b16 {%0,%1,%2,%3}, [%4];"
                 : "=r"(r[0]), "=r"(r[1]), "=r"(r[2]), "=r"(r[3]) : "r"(addr));
}
__device__ __forceinline__ void mma_bf16(float* d, const uint32_t* a,
                                         uint32_t b0, uint32_t b1) {
    asm volatile(
        "mma.sync.aligned.m16n8k16.row.col.f32.bf16.bf16.f32 "
        "{%0,%1,%2,%3}, {%4,%5,%6,%7}, {%8,%9}, {%0,%1,%2,%3};"
        : "+f"(d[0]), "+f"(d[1]), "+f"(d[2]), "+f"(d[3])
        : "r"(a[0]), "r"(a[1]), "r"(a[2]), "r"(a[3]), "r"(b0), "r"(b1));
}

// ================= CSR build =================
__global__ void zero_kernel() {
    int stride = gridDim.x * blockDim.x;
    int t0 = blockIdx.x * blockDim.x + threadIdx.x;
    for (int i = t0; i < NN; i += stride) g_deg[i] = 0;
    for (int i = t0; i < NG * DD; i += stride) g_pooled[i] = 0.f;
    for (int i = t0; i < NG; i += stride) g_cnt[i] = 0;
}
__global__ void hist_kernel(const int* __restrict__ dst, int E) {
    int i = blockIdx.x * blockDim.x + threadIdx.x;
    if (i < E) atomicAdd(&g_deg[dst[i]], 1);
}
__global__ void scan_kernel(int n) {
    __shared__ int s[1024];
    int t = threadIdx.x;
    int CH = (n + 1023) >> 10;
    int lo = t * CH, hi = min(lo + CH, n);
    int sum = 0;
    for (int i = lo; i < hi; i++) sum += g_deg[i];
    s[t] = sum;
    __syncthreads();
    for (int off = 1; off < 1024; off <<= 1) {
        int v = s[t];
        if (t >= off) v += s[t - off];
        __syncthreads();
        s[t] = v;
        __syncthreads();
    }
    int run = s[t] - sum;
    for (int i = lo; i < hi; i++) {
        g_rowptr[i] = run; g_cursor[i] = run; run += g_deg[i];
    }
    if (t == 1023) g_rowptr[n] = s[1023];
}
__global__ void scatter_kernel(const int* __restrict__ src,
                               const int* __restrict__ dst, int E) {
    int i = blockIdx.x * blockDim.x + threadIdx.x;
    if (i < E) {
        int d = dst[i];
        int pos = atomicAdd(&g_cursor[d], 1);
        g_csr[pos] = src[i];
    }
}

// ================= weight prep =================
// Image layout (per [layer][side]): B^T rows n (0..127), 128 bf16 per row
// (256B), stored as 16B chunks with chunk' = chunk ^ (n & 7).
__global__ void wprep_kernel(const float* __restrict__ Wl, const float* __restrict__ Wr) {
    int i = blockIdx.x * blockDim.x + threadIdx.x;   // NLAY*2*128*128
    if (i >= NLAY * 2 * 128 * 128) return;
    int l = i >> 15;
    int s = (i >> 14) & 1;
    int n = (i >> 7) & 127;
    int k = i & 127;
    const float* W = s ? Wr : Wl;
    float w = W[l * DD * DD + k * DD + n];
    __nv_bfloat16 hi = __float2bfloat16(w);
    __nv_bfloat16 lo = __float2bfloat16(w - __bfloat162float(hi));
    uint32_t chunk = (uint32_t)(k >> 3) ^ (uint32_t)(n & 7);
    uint32_t us_idx = (uint32_t)n * 128u + chunk * 8u + (uint32_t)(k & 7);
    g_Whi[l][s][us_idx] = __bfloat16_as_ushort(hi);
    g_Wlo[l][s][us_idx] = __bfloat16_as_ushort(lo);
}

// ================= tensor-core GEMM via mma.sync bf16 split-2 =================
// Block: 128(M) x 128(N), 256 threads (8 warps, 4x2), K=128.
// blockIdx.y = 0 -> Wl -> g_xl (+bl) ; 1 -> Wr -> g_xr (+br).
#define SM_AHI 0
#define SM_ALO 32768
#define SM_BHI 65536
#define SM_BLO 98304
#define SM_TOTAL 131072

__global__ void __launch_bounds__(256, 1) gemm_mma_kernel(
    const float* __restrict__ xext, int src_sel, int layer,
    const float* __restrict__ bl, const float* __restrict__ br, int n)
{
    extern __shared__ char smem[];
    uint32_t sb = smem_to_u32(smem);
    int tid = threadIdx.x;
    int w = tid >> 5;
    int l = tid & 31;
    int wm = w & 3;      // 0..3  -> rows wm*32
    int wn = w >> 2;     // 0..1  -> cols wn*64
    int row0 = blockIdx.x * 128;
    int sel = blockIdx.y;

    const float* A = (src_sel == 0) ? xext : (src_sel == 1 ? g_bufA : g_bufB);
    const float* bvec = (sel ? br : bl) + (size_t)layer * DD;
    float* C = sel ? g_xr : g_xl;

    // ---- load + split A tile (128 x 128 fp32 -> bf16 hi/lo, swizzled) ----
#pragma unroll
    for (int it = 0; it < 8; it++) {
        int c = tid + it * 256;          // chunk id 0..2047
        int r = c >> 4;
        int c8 = c & 15;
        float4 v0 = make_float4(0.f, 0.f, 0.f, 0.f), v1 = v0;
        int grow = row0 + r;
        if (grow < n) {
            const float* ap = A + (size_t)grow * DD + c8 * 8;
            v0 = *(const float4*)ap;
            v1 = *(const float4*)(ap + 4);
        }
        float f[8] = {v0.x, v0.y, v0.z, v0.w, v1.x, v1.y, v1.z, v1.w};
        uint32_t hi[4], lo[4];
#pragma unroll
        for (int j = 0; j < 4; j++) {
            __nv_bfloat16 h0 = __float2bfloat16(f[2 * j]);
            __nv_bfloat16 h1 = __float2bfloat16(f[2 * j + 1]);
            __nv_bfloat16 l0 = __float2bfloat16(f[2 * j]     - __bfloat162float(h0));
            __nv_bfloat16 l1 = __float2bfloat16(f[2 * j + 1] - __bfloat162float(h1));
            hi[j] = (uint32_t)__bfloat16_as_ushort(h0) | ((uint32_t)__bfloat16_as_ushort(h1) << 16);
            lo[j] = (uint32_t)__bfloat16_as_ushort(l0) | ((uint32_t)__bfloat16_as_ushort(l1) << 16);
        }
        uint32_t off = (uint32_t)r * 256u + (uint32_t)((c8 ^ (r & 7)) << 4);
        *(uint4*)(smem + SM_AHI + off) = make_uint4(hi[0], hi[1], hi[2], hi[3]);
        *(uint4*)(smem + SM_ALO + off) = make_uint4(lo[0], lo[1], lo[2], lo[3]);
    }
    // ---- copy pre-swizzled W images (hi+lo, 32KB each) ----
    {
        const uint4* srcH = (const uint4*)g_Whi[layer][sel];
        const uint4* srcL = (const uint4*)g_Wlo[layer][sel];
        uint4* dstH = (uint4*)(smem + SM_BHI);
        uint4* dstL = (uint4*)(smem + SM_BLO);
#pragma unroll
        for (int it = 0; it < 8; it++) {
            int idx = tid + it * 256;
            dstH[idx] = srcH[idx];
            dstL[idx] = srcL[idx];
        }
    }
    __syncthreads();

    // ---- per-lane ldmatrix base offsets ----
    int lr = l & 15;          // row within 16-row group
    int cb = l >> 4;          // 0/1: chunk +0 / +1
    // A rows for mt=0,1
    uint32_t arow[2], aoff[2], asw[2];
#pragma unroll
    for (int mt = 0; mt < 2; mt++) {
        arow[mt] = (uint32_t)(wm * 32 + mt * 16 + lr);
        aoff[mt] = arow[mt] * 256u;
        asw[mt]  = arow[mt] & 7u;
    }
    // B rows for np=0..3 (pairs of n8 tiles)
    uint32_t boff[4], bsw[4];
#pragma unroll
    for (int np = 0; np < 4; np++) {
        uint32_t brow = (uint32_t)(wn * 64 + np * 16 + lr);
        boff[np] = brow * 256u;
        bsw[np]  = brow & 7u;
    }

    float acc[2][8][4];
#pragma unroll
    for (int mt = 0; mt < 2; mt++)
#pragma unroll
        for (int nt = 0; nt < 8; nt++)
#pragma unroll
            for (int j = 0; j < 4; j++) acc[mt][nt][j] = 0.f;

    // ---- K loop: 8 steps of k16; 3 split products ----
#pragma unroll
    for (int ks = 0; ks < 8; ks++) {
        uint32_t kc = (uint32_t)(ks * 2 + cb);
        uint32_t ah[2][4], al[2][4];
#pragma unroll
        for (int mt = 0; mt < 2; mt++) {
            uint32_t off = aoff[mt] + ((kc ^ asw[mt]) << 4);
            ldsm_x4(ah[mt], sb + SM_AHI + off);
            ldsm_x4(al[mt], sb + SM_ALO + off);
        }
        uint32_t bh[4][4], blo[4][4];
#pragma unroll
        for (int np = 0; np < 4; np++) {
            uint32_t off = boff[np] + ((kc ^ bsw[np]) << 4);
            ldsm_x4(bh[np],  sb + SM_BHI + off);
            ldsm_x4(blo[np], sb + SM_BLO + off);
        }
#pragma unroll
        for (int mt = 0; mt < 2; mt++) {
#pragma unroll
            for (int nt = 0; nt < 8; nt++) {
                int np = nt >> 1, odd = nt & 1;
                uint32_t b0h = bh[np][odd],  b1h = bh[np][odd + 2];
                uint32_t b0l = blo[np][odd], b1l = blo[np][odd + 2];
                mma_bf16(acc[mt][nt], ah[mt], b0h, b1h);   // Ahi*Bhi
                mma_bf16(acc[mt][nt], ah[mt], b0l, b1l);   // Ahi*Blo
                mma_bf16(acc[mt][nt], al[mt], b0h, b1h);   // Alo*Bhi
            }
        }
    }

    // ---- epilogue ----
    int gid = l >> 2, tig = l & 3;
#pragma unroll
    for (int mt = 0; mt < 2; mt++) {
        int r0 = row0 + wm * 32 + mt * 16 + gid;
#pragma unroll
        for (int nt = 0; nt < 8; nt++) {
            int col = wn * 64 + nt * 8 + tig * 2;
            float bv0 = bvec[col], bv1 = bvec[col + 1];
            if (r0 < n) {
                float2 o = make_float2(acc[mt][nt][0] + bv0, acc[mt][nt][1] + bv1);
                *(float2*)(C + (size_t)r0 * DD + col) = o;
            }
            if (r0 + 8 < n) {
                float2 o = make_float2(acc[mt][nt][2] + bv0, acc[mt][nt][3] + bv1);
                *(float2*)(C + (size_t)(r0 + 8) * DD + col) = o;
            }
        }
    }
}

// ================= fused GATv2 edge phase =================
__global__ void __launch_bounds__(256) attn_kernel(
    const float* __restrict__ att, const float* __restrict__ bias,
    int dst_sel, int n)
{
    int gw = (blockIdx.x * blockDim.x + threadIdx.x) >> 5;
    if (gw >= n) return;
    int lane = threadIdx.x & 31;
    float* out = (dst_sel == 1) ? g_bufA : g_bufB;
    int v = gw;

    float4 xrv = *(const float4*)(g_xr + (size_t)v * DD + lane * 4);
    float4 a4  = *(const float4*)(att + lane * 4);
    float4 b4  = *(const float4*)(bias + lane * 4);

    float m = -3.402823466e38f;
    float den = 0.f;
    float4 acc = make_float4(0.f, 0.f, 0.f, 0.f);

    int e0 = g_rowptr[v], e1 = g_rowptr[v + 1];
    for (int e = e0; e <= e1; e++) {
        int u = (e < e1) ? g_csr[e] : v;
        float4 xu = *(const float4*)(g_xl + (size_t)u * DD + lane * 4);
        float t0 = xu.x + xrv.x; t0 = (t0 > 0.f) ? t0 : NEG_SLOPE * t0;
        float t1 = xu.y + xrv.y; t1 = (t1 > 0.f) ? t1 : NEG_SLOPE * t1;
        float t2 = xu.z + xrv.z; t2 = (t2 > 0.f) ? t2 : NEG_SLOPE * t2;
        float t3 = xu.w + xrv.w; t3 = (t3 > 0.f) ? t3 : NEG_SLOPE * t3;
        float s = a4.x * t0 + a4.y * t1 + a4.z * t2 + a4.w * t3;
        s += __shfl_xor_sync(0xffffffffu, s, 1);
        s += __shfl_xor_sync(0xffffffffu, s, 2);
        float nm = fmaxf(m, s);
        float c = __expf(m - nm);
        float p = __expf(s - nm);
        den = den * c + p;
        acc.x = acc.x * c + p * xu.x;
        acc.y = acc.y * c + p * xu.y;
        acc.z = acc.z * c + p * xu.z;
        acc.w = acc.w * c + p * xu.w;
        m = nm;
    }
    float inv = 1.f / den;
    float4 o;
    o.x = acc.x * inv + b4.x;
    o.y = acc.y * inv + b4.y;
    o.z = acc.z * inv + b4.z;
    o.w = acc.w * inv + b4.w;
    o.x = (o.x > 0.f) ? o.x : expm1f(o.x);
    o.y = (o.y > 0.f) ? o.y : expm1f(o.y);
    o.z = (o.z > 0.f) ? o.z : expm1f(o.z);
    o.w = (o.w > 0.f) ? o.w : expm1f(o.w);
    *(float4*)(out + (size_t)v * DD + lane * 4) = o;
}

// ================= pool + head =================
__global__ void pool_kernel(const int* __restrict__ batch, int n) {
    int i = blockIdx.x * blockDim.x + threadIdx.x;
    int node = i >> 5;
    if (node >= n) return;
    int lane = i & 31;
    int g = batch[node];
    float4 v = *(const float4*)(g_bufA + (size_t)node * DD + lane * 4);
    atomicAdd(&g_pooled[g * DD + lane * 4 + 0], v.x);
    atomicAdd(&g_pooled[g * DD + lane * 4 + 1], v.y);
    atomicAdd(&g_pooled[g * DD + lane * 4 + 2], v.z);
    atomicAdd(&g_pooled[g * DD + lane * 4 + 3], v.w);
    if (lane == 0) atomicAdd(&g_cnt[g], 1);
}
__global__ void head_kernel(const float* __restrict__ Wout,
                            const float* __restrict__ bout,
                            float* __restrict__ out) {
    int g = blockIdx.x;
    int lane = threadIdx.x;
    float invc = 1.f / fmaxf((float)g_cnt[g], 1.f);
    float part[NC];
#pragma unroll
    for (int c = 0; c < NC; c++) part[c] = 0.f;
    for (int col = lane; col < DD; col += 32) {
        float v = g_pooled[g * DD + col] * invc;
#pragma unroll
        for (int c = 0; c < NC; c++) part[c] += v * Wout[col * NC + c];
    }
#pragma unroll
    for (int c = 0; c < NC; c++) {
#pragma unroll
        for (int off = 16; off; off >>= 1)
            part[c] += __shfl_xor_sync(0xffffffffu, part[c], off);
    }
    if (lane == 0) {
        float lg[NC];
        float mx = -3.402823466e38f;
#pragma unroll
        for (int c = 0; c < NC; c++) { lg[c] = part[c] + bout[c]; mx = fmaxf(mx, lg[c]); }
        float se = 0.f;
#pragma unroll
        for (int c = 0; c < NC; c++) se += expf(lg[c] - mx);
        float lse = logf(se) + mx;
#pragma unroll
        for (int c = 0; c < NC; c++) out[g * NC + c] = lg[c] - lse;
    }
}

// ================= launch =================
extern "C" void kernel_launch(void* const* d_in, const int* in_sizes, int n_in,
                              void* d_out, int out_size) {
    const float* x     = (const float*)d_in[0];
    const int*   ei    = (const int*)d_in[1];
    const int*   batch = (const int*)d_in[2];
    const float* Wl    = (const float*)d_in[3];
    const float* bl    = (const float*)d_in[4];
    const float* Wr    = (const float*)d_in[5];
    const float* br    = (const float*)d_in[6];
    const float* att   = (const float*)d_in[7];
    const float* bias  = (const float*)d_in[8];
    const float* Wout  = (const float*)d_in[9];
    const float* bout  = (const float*)d_in[10];
    float* out = (float*)d_out;

    int N = in_sizes[0] / DD;
    int E = in_sizes[1] / 2;
    const int* srcp = ei;
    const int* dstp = ei + E;

    static int smem_set = 0;
    if (!smem_set) {
        cudaFuncSetAttribute(gemm_mma_kernel,
                             cudaFuncAttributeMaxDynamicSharedMemorySize, SM_TOTAL);
        smem_set = 1;
    }

    zero_kernel<<<256, 256>>>();
    hist_kernel<<<(E + 255) / 256, 256>>>(dstp, E);
    scan_kernel<<<1, 1024>>>(N);
    scatter_kernel<<<(E + 255) / 256, 256>>>(srcp, dstp, E);
    wprep_kernel<<<(NLAY * 2 * 128 * 128 + 255) / 256, 256>>>(Wl, Wr);

    for (int l = 0; l < 5; l++) {
        int src_sel = (l == 0) ? 0 : ((l & 1) ? 1 : 2);
        int dst_sel = (l & 1) ? 2 : 1;
        dim3 gg((N + 127) / 128, 2);
        gemm_mma_kernel<<<gg, 256, SM_TOTAL>>>(x, src_sel, l, bl, br, N);
        int blocks = (N * 32 + 255) / 256;
        attn_kernel<<<blocks, 256>>>(att + (size_t)l * DD,
                                     bias + (size_t)l * DD, dst_sel, N);
    }
    pool_kernel<<<(N * 32 + 255) / 256, 256>>>(batch, N);
    head_kernel<<<NG, 32>>>(Wout, bout, out);
}